// round 16
// baseline (speedup 1.0000x reference)
#include <cuda_runtime.h>
#include <cuda_bf16.h>
#include <cstdint>

#define N_PAIRS 500000
#define LMAX    4
#define NM      16
#define HID     32
#define NSPEC   4
#define NTILES  24            // B-fragment tiles per (l,s): L1:4, L2:8, L3:8, L4:4

// Scratch (allocation-free rule: __device__ globals)
__device__ int d_count[NSPEC];
__device__ int d_cursor[NSPEC];
__device__ int d_sorted[N_PAIRS];

// ---------------- block-local species dtype detection ----------------
__device__ __forceinline__ int detect_stride(const int* __restrict__ sp32,
                                             int tid, int* shflag) {
    if (tid == 0) *shflag = 0;
    __syncthreads();
    if (tid < 256 && sp32[2 * tid + 1] != 0) atomicOr(shflag, 1);
    __syncthreads();
    return *shflag ? 1 : 2;
}

// ---------------- sort-by-species (4 launches total incl. mlp) ----------------

__global__ void k_zero() {
    if (threadIdx.x < NSPEC) {
        d_count[threadIdx.x] = 0;
        d_cursor[threadIdx.x] = 0;
    }
}

__global__ void k_hist(const int* __restrict__ sp32) {
    __shared__ int cnt[NSPEC];
    __shared__ int flag;
    int tid = threadIdx.x;
    if (tid < NSPEC) cnt[tid] = 0;
    const int stride = detect_stride(sp32, tid, &flag);
    __syncthreads();
    int i = blockIdx.x * blockDim.x + tid;
    if (i < N_PAIRS) {
        int sp = sp32[i * stride] & 3;
        atomicAdd(&cnt[sp], 1);
    }
    __syncthreads();
    if (tid < NSPEC && cnt[tid] > 0) atomicAdd(&d_count[tid], cnt[tid]);
}

// scatter derives bucket offsets locally from d_count (no k_offsets launch)
__global__ void k_scatter(const int* __restrict__ sp32) {
    __shared__ int cnt[NSPEC];
    __shared__ int base[NSPEC];
    __shared__ int flag;
    int tid = threadIdx.x;
    if (tid < NSPEC) cnt[tid] = 0;
    const int stride = detect_stride(sp32, tid, &flag);
    __syncthreads();
    int i = blockIdx.x * blockDim.x + tid;
    int sp = 0;
    if (i < N_PAIRS) {
        sp = sp32[i * stride] & 3;
        atomicAdd(&cnt[sp], 1);
    }
    __syncthreads();
    if (tid < NSPEC) {
        int off = 0;                       // exclusive prefix of d_count[0..tid)
        for (int s = 0; s < tid; ++s) off += d_count[s];
        base[tid] = (cnt[tid] > 0) ? off + atomicAdd(&d_cursor[tid], cnt[tid]) : 0;
        cnt[tid] = 0;                      // reuse as local rank cursor
    }
    __syncthreads();
    if (i < N_PAIRS) {
        int r = atomicAdd(&cnt[sp], 1);
        d_sorted[base[sp] + r] = i;
    }
}

// ---------------- bf16 split helpers ----------------

// split (f0, f1) -> bf16x2 hi reg (lo half = f0) + bf16x2 residual reg
__device__ __forceinline__ void splitpack(float f0, float f1,
                                          uint32_t& hi, uint32_t& lo) {
    asm("cvt.rn.bf16x2.f32 %0, %2, %1;" : "=r"(hi) : "f"(f0), "f"(f1));
    uint32_t u0 = hi << 16;
    uint32_t u1 = hi & 0xFFFF0000u;
    float r0 = f0 - __uint_as_float(u0);
    float r1 = f1 - __uint_as_float(u1);
    asm("cvt.rn.bf16x2.f32 %0, %2, %1;" : "=r"(lo) : "f"(r0), "f"(r1));
}

// silu via tanh.approx (1 MUFU op): silu(v) = fma(0.5v, tanh(0.5v), 0.5v)
__device__ __forceinline__ float silu(float v) {
    float h = 0.5f * v;
    float t;
    asm("tanh.approx.f32 %0, %1;" : "=f"(t) : "f"(h));
    return fmaf(h, t, h);
}

// ---------------- mma.sync (legacy HMMA; NON-volatile: let the scheduler move it) ----

__device__ __forceinline__ void mma16816(float* c, const uint32_t* a,
                                         uint32_t b0, uint32_t b1) {
    asm("mma.sync.aligned.m16n8k16.row.col.f32.bf16.bf16.f32 "
        "{%0,%1,%2,%3}, {%4,%5,%6,%7}, {%8,%9}, {%0,%1,%2,%3};"
        : "+f"(c[0]), "+f"(c[1]), "+f"(c[2]), "+f"(c[3])
        : "r"(a[0]), "r"(a[1]), "r"(a[2]), "r"(a[3]), "r"(b0), "r"(b1));
}

// C(m16n8) thread mapping == A(m16n8k16) k-halves: chain layers in registers.
__device__ __forceinline__ void epilogue(float acc[][4],
                                         uint32_t Ah[2][4], uint32_t Al[2][4]) {
#pragma unroll
    for (int j = 0; j < 2; ++j) {
        float s00 = silu(acc[2*j][0]),   s01 = silu(acc[2*j][1]);
        float s02 = silu(acc[2*j][2]),   s03 = silu(acc[2*j][3]);
        float s10 = silu(acc[2*j+1][0]), s11 = silu(acc[2*j+1][1]);
        float s12 = silu(acc[2*j+1][2]), s13 = silu(acc[2*j+1][3]);
        splitpack(s00, s01, Ah[j][0], Al[j][0]);
        splitpack(s02, s03, Ah[j][1], Al[j][1]);
        splitpack(s10, s11, Ah[j][2], Al[j][2]);
        splitpack(s12, s13, Ah[j][3], Al[j][3]);
    }
}

// Term-major split-MMA group over NN fragments:
// same-accumulator reuse spaced by NN independent HMMAs (latency covered).
template <int NN>
__device__ __forceinline__ void mma_group(float acc[][4], const uint32_t* Ah,
                                          const uint32_t* Al, const uint4* w) {
#pragma unroll
    for (int n = 0; n < NN; ++n) mma16816(acc[n], Ah, w[n].x, w[n].y);  // hi*Wh
#pragma unroll
    for (int n = 0; n < NN; ++n) mma16816(acc[n], Al, w[n].x, w[n].y);  // lo*Wh
#pragma unroll
    for (int n = 0; n < NN; ++n) mma16816(acc[n], Ah, w[n].z, w[n].w);  // hi*Wl
}

// ---------------- main MLP kernel (fragment prep fused in) ----------------
// B fragment (mma.m16n8k16, col-major B = W[k][n]):
//   lane: q = lane&3, col = lane>>2; k0 = ktile*16 + 2q; n = ntile*8 + col
//   reg0 = {W[k0][n], W[k0+1][n]}, reg1 = {W[k0+8][n], W[k0+9][n]}
// Packed smem fragment: uint4 {hi.reg0, hi.reg1, lo.reg0, lo.reg1} (1 LDS.128)
// Tile order: L1: 0..3 (ntile, K=16); L2: 4 + n*2 + k; L3: 12 + n*2 + k;
//             L4: 20 + n*2 + k (ntile 0..1, W4 is [32][16]).

__global__ void __launch_bounds__(256, 3)
k_mlp(const float* __restrict__ xg,
      const float* __restrict__ W1, const float* __restrict__ W2,
      const float* __restrict__ W3, const float* __restrict__ W4,
      float* __restrict__ out) {
    const int ls = blockIdx.y;
    const int l = ls >> 2, s = ls & 3;

    __shared__ uint4 wfr[NTILES * 32];   // 12 KB

    // fused fragment prep: each CTA builds its (l,s) fragments into smem
    for (int slot = threadIdx.x; slot < NTILES * 32; slot += 256) {
        const int tile = slot >> 5, lane = slot & 31;
        const int q = lane & 3, col = lane >> 2;
        const float* W;
        int N, nt, kt;
        if (tile < 4)       { W = W1 + ls * 512;  N = 32; nt = tile;           kt = 0; }
        else if (tile < 12) { W = W2 + ls * 1024; N = 32; nt = (tile-4)  >> 1; kt = (tile-4)  & 1; }
        else if (tile < 20) { W = W3 + ls * 1024; N = 32; nt = (tile-12) >> 1; kt = (tile-12) & 1; }
        else                { W = W4 + ls * 512;  N = 16; nt = (tile-20) >> 1; kt = (tile-20) & 1; }
        const int k0 = kt * 16 + q * 2;
        const int n  = nt * 8 + col;
        float e0 = W[(k0 + 0) * N + n], e1 = W[(k0 + 1) * N + n];
        float e2 = W[(k0 + 8) * N + n], e3 = W[(k0 + 9) * N + n];
        uint4 f;
        splitpack(e0, e1, f.x, f.z);
        splitpack(e2, e3, f.y, f.w);
        wfr[slot] = f;
    }

    // bucket offset + count from d_count (local prefix over <=4)
    int beg = 0;
#pragma unroll
    for (int t = 0; t < NSPEC; ++t) if (t < s) beg += d_count[t];
    const int cnt = d_count[s];
    __syncthreads();

    const int lane = threadIdx.x & 31, wid = threadIdx.x >> 5;
    const int q = lane & 3, g = lane >> 2;
    const int ntile = (cnt + 15) >> 4;

    for (int t = blockIdx.x * 8 + wid; t < ntile; t += gridDim.x * 8) {
        int r0 = t * 16 + g;     if (r0 >= cnt) r0 = cnt - 1;
        int r1 = t * 16 + g + 8; if (r1 >= cnt) r1 = cnt - 1;
        const int i0 = d_sorted[beg + r0];
        const int i1 = d_sorted[beg + r1];
        const float* p0 = xg + (size_t)i0 * (LMAX * NM) + l * NM;
        const float* p1 = xg + (size_t)i1 * (LMAX * NM) + l * NM;

        // A fragment: rows {g, g+8}, cols {2q,2q+1} and {2q+8,2q+9}
        float2 v00 = *reinterpret_cast<const float2*>(p0 + 2 * q);
        float2 v01 = *reinterpret_cast<const float2*>(p0 + 2 * q + 8);
        float2 v10 = *reinterpret_cast<const float2*>(p1 + 2 * q);
        float2 v11 = *reinterpret_cast<const float2*>(p1 + 2 * q + 8);

        uint32_t Ah[2][4], Al[2][4];
        splitpack(v00.x, v00.y, Ah[0][0], Al[0][0]);
        splitpack(v10.x, v10.y, Ah[0][1], Al[0][1]);
        splitpack(v01.x, v01.y, Ah[0][2], Al[0][2]);
        splitpack(v11.x, v11.y, Ah[0][3], Al[0][3]);

        float acc[4][4];
        uint4 w[4];

        // ---- L1: K=16, tiles 0..3 ----
#pragma unroll
        for (int n = 0; n < 4; ++n) {
#pragma unroll
            for (int e = 0; e < 4; ++e) acc[n][e] = 0.f;
            w[n] = wfr[n * 32 + lane];
        }
        mma_group<4>(acc, Ah[0], Al[0], w);
        epilogue(acc, Ah, Al);

        // ---- L2, L3: K=32, tiles 4.. and 12.. ----
#pragma unroll
        for (int base = 4; base <= 12; base += 8) {
#pragma unroll
            for (int n = 0; n < 4; ++n)
#pragma unroll
                for (int e = 0; e < 4; ++e) acc[n][e] = 0.f;
#pragma unroll
            for (int k = 0; k < 2; ++k) {
#pragma unroll
                for (int n = 0; n < 4; ++n) w[n] = wfr[(base + n * 2 + k) * 32 + lane];
                mma_group<4>(acc, Ah[k], Al[k], w);
            }
            epilogue(acc, Ah, Al);
        }

        // ---- L4: K=32, N=16, tiles 20..23 ----
#pragma unroll
        for (int n = 0; n < 2; ++n)
#pragma unroll
            for (int e = 0; e < 4; ++e) acc[n][e] = 0.f;
#pragma unroll
        for (int k = 0; k < 2; ++k) {
#pragma unroll
            for (int n = 0; n < 2; ++n) w[n] = wfr[(20 + n * 2 + k) * 32 + lane];
            mma_group<2>(acc, Ah[k], Al[k], w);
        }

        // ---- write out: C(m16n8) mapping, 2 rows x 2 ntiles x float2 ----
        float* o0 = out + (size_t)i0 * (LMAX * NM) + l * NM;
        float* o1 = out + (size_t)i1 * (LMAX * NM) + l * NM;
        *reinterpret_cast<float2*>(o0 + 2 * q)     = make_float2(acc[0][0], acc[0][1]);
        *reinterpret_cast<float2*>(o0 + 2 * q + 8) = make_float2(acc[1][0], acc[1][1]);
        *reinterpret_cast<float2*>(o1 + 2 * q)     = make_float2(acc[0][2], acc[0][3]);
        *reinterpret_cast<float2*>(o1 + 2 * q + 8) = make_float2(acc[1][2], acc[1][3]);
    }
}

// ---------------- launch ----------------

extern "C" void kernel_launch(void* const* d_in, const int* in_sizes, int n_in,
                              void* d_out, int out_size) {
    const float* x   = (const float*)d_in[0];
    const int*   sp  = (const int*)d_in[1];   // int32 or int64 — detected on device
    const float* W1  = (const float*)d_in[2];
    const float* W2  = (const float*)d_in[3];
    const float* W3  = (const float*)d_in[4];
    const float* W4  = (const float*)d_in[5];
    float*       out = (float*)d_out;

    const int nblk = (N_PAIRS + 255) / 256;

    k_zero<<<1, 32>>>();
    k_hist<<<nblk, 256>>>(sp);
    k_scatter<<<nblk, 256>>>(sp);

    // 27 x 16 = 432 CTAs = 3/SM one wave; 8 warps per CTA
    dim3 grid(27, LMAX * NSPEC);
    k_mlp<<<grid, 256>>>(x, W1, W2, W3, W4, out);
}

// round 17
// speedup vs baseline: 1.3152x; 1.3152x over previous
#include <cuda_runtime.h>
#include <cuda_bf16.h>
#include <cstdint>

#define N_PAIRS 500000
#define LMAX    4
#define NM      16
#define HID     32
#define NSPEC   4
#define NTILES  24            // B-fragment tiles per (l,s): L1:4, L2:8, L3:8, L4:4

// Scratch (allocation-free rule: __device__ globals)
__device__ int d_count[NSPEC];
__device__ int d_cursor[NSPEC];
__device__ int d_sorted[N_PAIRS];

// ---------------- block-local species dtype detection ----------------
__device__ __forceinline__ int detect_stride(const int* __restrict__ sp32,
                                             int tid, int* shflag) {
    if (tid == 0) *shflag = 0;
    __syncthreads();
    if (tid < 256 && sp32[2 * tid + 1] != 0) atomicOr(shflag, 1);
    __syncthreads();
    return *shflag ? 1 : 2;
}

// ---------------- sort-by-species (4 launches total incl. mlp) ----------------

__global__ void k_zero() {
    if (threadIdx.x < NSPEC) {
        d_count[threadIdx.x] = 0;
        d_cursor[threadIdx.x] = 0;
    }
}

__global__ void k_hist(const int* __restrict__ sp32) {
    __shared__ int cnt[NSPEC];
    __shared__ int flag;
    int tid = threadIdx.x;
    if (tid < NSPEC) cnt[tid] = 0;
    const int stride = detect_stride(sp32, tid, &flag);
    __syncthreads();
    int i = blockIdx.x * blockDim.x + tid;
    if (i < N_PAIRS) {
        int sp = sp32[i * stride] & 3;
        atomicAdd(&cnt[sp], 1);
    }
    __syncthreads();
    if (tid < NSPEC && cnt[tid] > 0) atomicAdd(&d_count[tid], cnt[tid]);
}

// scatter derives bucket offsets locally from d_count (no k_offsets launch)
__global__ void k_scatter(const int* __restrict__ sp32) {
    __shared__ int cnt[NSPEC];
    __shared__ int base[NSPEC];
    __shared__ int flag;
    int tid = threadIdx.x;
    if (tid < NSPEC) cnt[tid] = 0;
    const int stride = detect_stride(sp32, tid, &flag);
    __syncthreads();
    int i = blockIdx.x * blockDim.x + tid;
    int sp = 0;
    if (i < N_PAIRS) {
        sp = sp32[i * stride] & 3;
        atomicAdd(&cnt[sp], 1);
    }
    __syncthreads();
    if (tid < NSPEC) {
        int off = 0;                       // exclusive prefix of d_count[0..tid)
        for (int s = 0; s < tid; ++s) off += d_count[s];
        base[tid] = (cnt[tid] > 0) ? off + atomicAdd(&d_cursor[tid], cnt[tid]) : 0;
        cnt[tid] = 0;                      // reuse as local rank cursor
    }
    __syncthreads();
    if (i < N_PAIRS) {
        int r = atomicAdd(&cnt[sp], 1);
        d_sorted[base[sp] + r] = i;
    }
}

// ---------------- bf16 split helpers ----------------

// split (f0, f1) -> bf16x2 hi reg (lo half = f0) + bf16x2 residual reg
__device__ __forceinline__ void splitpack(float f0, float f1,
                                          uint32_t& hi, uint32_t& lo) {
    asm("cvt.rn.bf16x2.f32 %0, %2, %1;" : "=r"(hi) : "f"(f0), "f"(f1));
    uint32_t u0 = hi << 16;
    uint32_t u1 = hi & 0xFFFF0000u;
    float r0 = f0 - __uint_as_float(u0);
    float r1 = f1 - __uint_as_float(u1);
    asm("cvt.rn.bf16x2.f32 %0, %2, %1;" : "=r"(lo) : "f"(r0), "f"(r1));
}

// silu via tanh.approx (1 MUFU op): silu(v) = fma(0.5v, tanh(0.5v), 0.5v)
__device__ __forceinline__ float silu(float v) {
    float h = 0.5f * v;
    float t;
    asm("tanh.approx.f32 %0, %1;" : "=f"(t) : "f"(h));
    return fmaf(h, t, h);
}

// ---------------- mma.sync (legacy HMMA; volatile = proven-safe codegen) ----------

__device__ __forceinline__ void mma16816(float* c, const uint32_t* a,
                                         uint32_t b0, uint32_t b1) {
    asm volatile(
        "mma.sync.aligned.m16n8k16.row.col.f32.bf16.bf16.f32 "
        "{%0,%1,%2,%3}, {%4,%5,%6,%7}, {%8,%9}, {%0,%1,%2,%3};"
        : "+f"(c[0]), "+f"(c[1]), "+f"(c[2]), "+f"(c[3])
        : "r"(a[0]), "r"(a[1]), "r"(a[2]), "r"(a[3]), "r"(b0), "r"(b1));
}

// Two interleaved 3-term split-MMA chains: same-accumulator reuse at
// distance 2 (vs 1 in R14's mma3) — only 2 uint4 fragments live at once.
__device__ __forceinline__ void mma3x2(float* a0, float* a1,
                                       const uint32_t* Ah, const uint32_t* Al,
                                       uint4 w0, uint4 w1) {
    mma16816(a0, Ah, w0.x, w0.y);   // hi*Wh  (chain 0)
    mma16816(a1, Ah, w1.x, w1.y);   // hi*Wh  (chain 1)
    mma16816(a0, Al, w0.x, w0.y);   // lo*Wh
    mma16816(a1, Al, w1.x, w1.y);
    mma16816(a0, Ah, w0.z, w0.w);   // hi*Wl
    mma16816(a1, Ah, w1.z, w1.w);
}

// C(m16n8) thread mapping == A(m16n8k16) k-halves: chain layers in registers.
__device__ __forceinline__ void epilogue(float acc[][4],
                                         uint32_t Ah[2][4], uint32_t Al[2][4]) {
#pragma unroll
    for (int j = 0; j < 2; ++j) {
        float s00 = silu(acc[2*j][0]),   s01 = silu(acc[2*j][1]);
        float s02 = silu(acc[2*j][2]),   s03 = silu(acc[2*j][3]);
        float s10 = silu(acc[2*j+1][0]), s11 = silu(acc[2*j+1][1]);
        float s12 = silu(acc[2*j+1][2]), s13 = silu(acc[2*j+1][3]);
        splitpack(s00, s01, Ah[j][0], Al[j][0]);
        splitpack(s02, s03, Ah[j][1], Al[j][1]);
        splitpack(s10, s11, Ah[j][2], Al[j][2]);
        splitpack(s12, s13, Ah[j][3], Al[j][3]);
    }
}

// ---------------- main MLP kernel (fragment prep fused in) ----------------
// B fragment (mma.m16n8k16, col-major B = W[k][n]):
//   lane: q = lane&3, col = lane>>2; k0 = ktile*16 + 2q; n = ntile*8 + col
//   reg0 = {W[k0][n], W[k0+1][n]}, reg1 = {W[k0+8][n], W[k0+9][n]}
// Packed smem fragment: uint4 {hi.reg0, hi.reg1, lo.reg0, lo.reg1} (1 LDS.128)
// Tile order: L1: 0..3 (ntile, K=16); L2: 4 + n*2 + k; L3: 12 + n*2 + k;
//             L4: 20 + n*2 + k (ntile 0..1, W4 is [32][16]).

__global__ void __launch_bounds__(256, 3)   // ~85-reg cap
k_mlp(const float* __restrict__ xg,
      const float* __restrict__ W1, const float* __restrict__ W2,
      const float* __restrict__ W3, const float* __restrict__ W4,
      float* __restrict__ out) {
    const int ls = blockIdx.y;
    const int l = ls >> 2, s = ls & 3;

    __shared__ uint4 wfr[NTILES * 32];   // 12 KB

    // fused fragment prep: each CTA builds its (l,s) fragments into smem
    for (int slot = threadIdx.x; slot < NTILES * 32; slot += 256) {
        const int tile = slot >> 5, lane = slot & 31;
        const int q = lane & 3, col = lane >> 2;
        const float* W;
        int N, nt, kt;
        if (tile < 4)       { W = W1 + ls * 512;  N = 32; nt = tile;           kt = 0; }
        else if (tile < 12) { W = W2 + ls * 1024; N = 32; nt = (tile-4)  >> 1; kt = (tile-4)  & 1; }
        else if (tile < 20) { W = W3 + ls * 1024; N = 32; nt = (tile-12) >> 1; kt = (tile-12) & 1; }
        else                { W = W4 + ls * 512;  N = 16; nt = (tile-20) >> 1; kt = (tile-20) & 1; }
        const int k0 = kt * 16 + q * 2;
        const int n  = nt * 8 + col;
        float e0 = W[(k0 + 0) * N + n], e1 = W[(k0 + 1) * N + n];
        float e2 = W[(k0 + 8) * N + n], e3 = W[(k0 + 9) * N + n];
        uint4 f;
        splitpack(e0, e1, f.x, f.z);
        splitpack(e2, e3, f.y, f.w);
        wfr[slot] = f;
    }

    // bucket offset + count from d_count (local prefix over <=4)
    int beg = 0;
#pragma unroll
    for (int t = 0; t < NSPEC; ++t) if (t < s) beg += d_count[t];
    const int cnt = d_count[s];
    __syncthreads();

    const int lane = threadIdx.x & 31, wid = threadIdx.x >> 5;
    const int q = lane & 3, g = lane >> 2;
    const int ntile = (cnt + 15) >> 4;
    const int tstride = gridDim.x * 8;

    int t = blockIdx.x * 8 + wid;

    // ---- prefetch registers (next tile's indices + x data) ----
    int ni0 = 0, ni1 = 0;
    float2 nv00, nv01, nv10, nv11;
    if (t < ntile) {
        int r0 = t * 16 + g;     if (r0 >= cnt) r0 = cnt - 1;
        int r1 = t * 16 + g + 8; if (r1 >= cnt) r1 = cnt - 1;
        ni0 = d_sorted[beg + r0];
        ni1 = d_sorted[beg + r1];
        const float* p0 = xg + (size_t)ni0 * (LMAX * NM) + l * NM;
        const float* p1 = xg + (size_t)ni1 * (LMAX * NM) + l * NM;
        nv00 = *reinterpret_cast<const float2*>(p0 + 2 * q);
        nv01 = *reinterpret_cast<const float2*>(p0 + 2 * q + 8);
        nv10 = *reinterpret_cast<const float2*>(p1 + 2 * q);
        nv11 = *reinterpret_cast<const float2*>(p1 + 2 * q + 8);
    }

    for (; t < ntile; t += tstride) {
        const int i0 = ni0, i1 = ni1;

        // build current A fragments from prefetched data
        uint32_t Ah[2][4], Al[2][4];
        splitpack(nv00.x, nv00.y, Ah[0][0], Al[0][0]);
        splitpack(nv10.x, nv10.y, Ah[0][1], Al[0][1]);
        splitpack(nv01.x, nv01.y, Ah[0][2], Al[0][2]);
        splitpack(nv11.x, nv11.y, Ah[0][3], Al[0][3]);

        // kick off next tile's loads NOW — latency hidden behind MMA chain
        const int t2 = t + tstride;
        if (t2 < ntile) {
            int r0 = t2 * 16 + g;     if (r0 >= cnt) r0 = cnt - 1;
            int r1 = t2 * 16 + g + 8; if (r1 >= cnt) r1 = cnt - 1;
            ni0 = d_sorted[beg + r0];
            ni1 = d_sorted[beg + r1];
            const float* p0 = xg + (size_t)ni0 * (LMAX * NM) + l * NM;
            const float* p1 = xg + (size_t)ni1 * (LMAX * NM) + l * NM;
            nv00 = *reinterpret_cast<const float2*>(p0 + 2 * q);
            nv01 = *reinterpret_cast<const float2*>(p0 + 2 * q + 8);
            nv10 = *reinterpret_cast<const float2*>(p1 + 2 * q);
            nv11 = *reinterpret_cast<const float2*>(p1 + 2 * q + 8);
        }

        float acc[4][4];

        // ---- L1: K=16, tiles 0..3 ----
#pragma unroll
        for (int n = 0; n < 4; ++n)
#pragma unroll
            for (int e = 0; e < 4; ++e) acc[n][e] = 0.f;
        mma3x2(acc[0], acc[1], Ah[0], Al[0], wfr[0 * 32 + lane], wfr[1 * 32 + lane]);
        mma3x2(acc[2], acc[3], Ah[0], Al[0], wfr[2 * 32 + lane], wfr[3 * 32 + lane]);
        epilogue(acc, Ah, Al);

        // ---- L2, L3: K=32, tiles 4.. and 12.. ----
#pragma unroll
        for (int base = 4; base <= 12; base += 8) {
#pragma unroll
            for (int n = 0; n < 4; ++n)
#pragma unroll
                for (int e = 0; e < 4; ++e) acc[n][e] = 0.f;
#pragma unroll
            for (int k = 0; k < 2; ++k) {
                mma3x2(acc[0], acc[1], Ah[k], Al[k],
                       wfr[(base + 0 * 2 + k) * 32 + lane],
                       wfr[(base + 1 * 2 + k) * 32 + lane]);
                mma3x2(acc[2], acc[3], Ah[k], Al[k],
                       wfr[(base + 2 * 2 + k) * 32 + lane],
                       wfr[(base + 3 * 2 + k) * 32 + lane]);
            }
            epilogue(acc, Ah, Al);
        }

        // ---- L4: K=32, N=16, tiles 20..23 ----
#pragma unroll
        for (int n = 0; n < 2; ++n)
#pragma unroll
            for (int e = 0; e < 4; ++e) acc[n][e] = 0.f;
#pragma unroll
        for (int k = 0; k < 2; ++k) {
            mma3x2(acc[0], acc[1], Ah[k], Al[k],
                   wfr[(20 + 0 * 2 + k) * 32 + lane],
                   wfr[(20 + 1 * 2 + k) * 32 + lane]);
        }

        // ---- write out: C(m16n8) mapping, 2 rows x 2 ntiles x float2 ----
        float* o0 = out + (size_t)i0 * (LMAX * NM) + l * NM;
        float* o1 = out + (size_t)i1 * (LMAX * NM) + l * NM;
        *reinterpret_cast<float2*>(o0 + 2 * q)     = make_float2(acc[0][0], acc[0][1]);
        *reinterpret_cast<float2*>(o0 + 2 * q + 8) = make_float2(acc[1][0], acc[1][1]);
        *reinterpret_cast<float2*>(o1 + 2 * q)     = make_float2(acc[0][2], acc[0][3]);
        *reinterpret_cast<float2*>(o1 + 2 * q + 8) = make_float2(acc[1][2], acc[1][3]);
    }
}

// ---------------- launch ----------------

extern "C" void kernel_launch(void* const* d_in, const int* in_sizes, int n_in,
                              void* d_out, int out_size) {
    const float* x   = (const float*)d_in[0];
    const int*   sp  = (const int*)d_in[1];   // int32 or int64 — detected on device
    const float* W1  = (const float*)d_in[2];
    const float* W2  = (const float*)d_in[3];
    const float* W3  = (const float*)d_in[4];
    const float* W4  = (const float*)d_in[5];
    float*       out = (float*)d_out;

    const int nblk = (N_PAIRS + 255) / 256;

    k_zero<<<1, 32>>>();
    k_hist<<<nblk, 256>>>(sp);
    k_scatter<<<nblk, 256>>>(sp);

    // 27 x 16 = 432 CTAs = 3/SM one wave; 8 warps per CTA
    dim3 grid(27, LMAX * NSPEC);
    k_mlp<<<grid, 256>>>(x, W1, W2, W3, W4, out);
}